// round 6
// baseline (speedup 1.0000x reference)
#include <cuda_runtime.h>
#include <cuda_fp16.h>
#include <stdint.h>

// RNNWithCheckpoint: T=512, B=128, H=1024, L=4 multi-layer tanh RNN.
// R4: persistent kernel, warp-specialized producer/consumer pipeline.
//   warps 0-3: MMA consumers (32m x 64n each, one per SMSP)
//   warps 4-7: cp.async producers, 3-buffer mbarrier pipeline (no syncthreads
//   in mainloop). XOR-swizzled SMEM (no pad). 128 CTAs = 4 layers x 16
//   n-tiles(64) x 2 k-halves (ih|hh); 2-CTA-cluster DSMEM reduce; tanh fused.

#define T_STEPS 512
#define BATCH   128
#define HID     1024
#define LAYERS  4
#define NCTA    128

#define SM_W    0                      // 64 x 2048B swizzled = 131072
#define SM_A(b) (131072 + (b) * 32768) // 3 bufs: 128 rows x 256B swizzled
#define SM_SP   131072                 // partial 64 x 68 fp32, aliases buf0
#define SM_MBAR 229376                 // full[0..2], empty[0..2]
#define SMEM_BYTES 229440

// Static device scratch (no cudaMalloc allowed)
__device__ __align__(16) __half g_Wh[LAYERS * 2 * HID * HID];   // [l][ks][n][k]
__device__ __align__(16) __half g_xh[(size_t)T_STEPS * BATCH * HID];
__device__ __align__(16) float  g_bias[LAYERS * HID];
__device__ __align__(16) __half g_act[2][LAYERS * BATCH * HID]; // parity bufs
__device__ unsigned g_flags[NCTA * 32];

// ------------------------------------------------------------- helpers ----
__device__ __forceinline__ uint32_t smem_u32(const void* p) {
    uint32_t a;
    asm("{ .reg .u64 t; cvta.to.shared.u64 t, %1; cvt.u32.u64 %0, t; }"
        : "=r"(a) : "l"(p));
    return a;
}
__device__ __forceinline__ void cp16(uint32_t dst, const void* src) {
    asm volatile("cp.async.cg.shared.global [%0], [%1], 16;"
                 :: "r"(dst), "l"(src) : "memory");
}
__device__ __forceinline__ void ldsm4(uint32_t* r, uint32_t a) {
    asm volatile("ldmatrix.sync.aligned.m8n8.x4.shared.b16 {%0,%1,%2,%3}, [%4];"
                 : "=r"(r[0]), "=r"(r[1]), "=r"(r[2]), "=r"(r[3]) : "r"(a));
}
__device__ __forceinline__ void mma16816(float* c, const uint32_t* a,
                                         uint32_t b0, uint32_t b1) {
    asm volatile(
        "mma.sync.aligned.m16n8k16.row.col.f32.f16.f16.f32 "
        "{%0,%1,%2,%3}, {%4,%5,%6,%7}, {%8,%9}, {%0,%1,%2,%3};"
        : "+f"(c[0]), "+f"(c[1]), "+f"(c[2]), "+f"(c[3])
        : "r"(a[0]), "r"(a[1]), "r"(a[2]), "r"(a[3]), "r"(b0), "r"(b1));
}
__device__ __forceinline__ void mbar_init(uint32_t m, uint32_t cnt) {
    asm volatile("mbarrier.init.shared.b64 [%0], %1;" :: "r"(m), "r"(cnt) : "memory");
}
__device__ __forceinline__ void mbar_wait(uint32_t m, uint32_t par) {
    asm volatile(
        "{\n\t.reg .pred P;\n"
        "W%=:\n\t"
        "mbarrier.try_wait.parity.acquire.cta.shared::cta.b64 P, [%0], %1, 0x989680;\n\t"
        "@P bra D%=;\n\t"
        "bra W%=;\n"
        "D%=:\n\t}"
        :: "r"(m), "r"(par) : "memory");
}
__device__ __forceinline__ void mbar_arrive(uint32_t m) {
    asm volatile("mbarrier.arrive.shared.b64 _, [%0];" :: "r"(m) : "memory");
}
__device__ __forceinline__ void cp_arrive(uint32_t m) {
    asm volatile("cp.async.mbarrier.arrive.noinc.shared.b64 [%0];"
                 :: "r"(m) : "memory");
}
__device__ __forceinline__ uint32_t mapa_u32(uint32_t a, uint32_t rk) {
    uint32_t o;
    asm("mapa.shared::cluster.u32 %0, %1, %2;" : "=r"(o) : "r"(a), "r"(rk));
    return o;
}
__device__ __forceinline__ float2 ld_dsmem2(uint32_t a) {
    float2 v;
    asm volatile("ld.shared::cluster.v2.f32 {%0,%1}, [%2];"
                 : "=f"(v.x), "=f"(v.y) : "r"(a) : "memory");
    return v;
}

// ---------------------------------------------------------------- prep ----
__global__ void __launch_bounds__(256) prep_kernel(
    const float* __restrict__ x,
    const float* __restrict__ Wih, const float* __restrict__ Whh,
    const float* __restrict__ bih, const float* __restrict__ bhh)
{
    int tid  = blockIdx.x * blockDim.x + threadIdx.x;
    int nthr = gridDim.x * blockDim.x;
    const int NW = LAYERS * HID * HID;
    for (int i = tid; i < NW; i += nthr) {
        int l  = i >> 20;
        int nk = i & (HID * HID - 1);
        g_Wh[((size_t)(l * 2 + 0) << 20) + nk] = __float2half(Wih[i]);
        g_Wh[((size_t)(l * 2 + 1) << 20) + nk] = __float2half(Whh[i]);
    }
    const size_t NX4 = (size_t)T_STEPS * BATCH * HID / 4;
    for (size_t i = tid; i < NX4; i += nthr) {
        float4 v = *(const float4*)(x + i * 4);
        *(__half2*)&g_xh[i * 4]     = __floats2half2_rn(v.x, v.y);
        *(__half2*)&g_xh[i * 4 + 2] = __floats2half2_rn(v.z, v.w);
    }
    for (int i = tid; i < LAYERS * HID; i += nthr) g_bias[i] = bih[i] + bhh[i];
    for (int i = tid; i < LAYERS * BATCH * HID; i += nthr) {
        g_act[0][i] = __float2half(0.0f);
        g_act[1][i] = __float2half(0.0f);
    }
    for (int i = tid; i < NCTA * 32; i += nthr) g_flags[i] = 0;
}

// ---------------------------------------------------------- grid barrier --
__device__ __forceinline__ void grid_barrier(unsigned target, int bx)
{
    __syncthreads();
    if (threadIdx.x < 32) {
        if (threadIdx.x == 0) {
            __threadfence();
            atomicExch(&g_flags[bx * 32], target);
        }
        const volatile unsigned* f = g_flags;
        int i0 = threadIdx.x * 4;
        for (;;) {
            bool ok = (f[(i0 + 0) * 32] >= target) & (f[(i0 + 1) * 32] >= target) &
                      (f[(i0 + 2) * 32] >= target) & (f[(i0 + 3) * 32] >= target);
            if (__all_sync(0xffffffffu, ok)) break;
            __nanosleep(60);
        }
        __threadfence();
    }
    __syncthreads();
}

// ----------------------------------------------------------- persistent ---
__global__ void __launch_bounds__(256) __cluster_dims__(2, 1, 1)
rnn_persistent(float* __restrict__ out)
{
    extern __shared__ char sh[];
    const uint32_t sb = smem_u32(sh);

    const int bx   = blockIdx.x;
    const int l    = bx >> 5;
    const int nt   = (bx >> 1) & 15;
    const int rank = bx & 1;
    const int tid  = threadIdx.x;
    const int wid  = tid >> 5, lane = tid & 31;
    const bool is_mma = (wid < 4);

    // mbarriers: full count = 128 producer threads, empty = 128 consumer thr
    if (tid == 0) {
        #pragma unroll
        for (int b = 0; b < 3; b++) {
            mbar_init(sb + SM_MBAR + b * 8, 128);       // full
            mbar_init(sb + SM_MBAR + 24 + b * 8, 128);  // empty
        }
    }
    __syncthreads();

    // ---- resident weight slice: 64 n-rows x 1024 k halves, XOR-swizzled
    {
        const __half* wsrc = g_Wh + (((size_t)(l * 2 + rank) * HID) + nt * 64) * HID;
        for (int i = tid; i < 8192; i += 256) {
            int n = i >> 7, u = i & 127;
            cp16(sb + SM_W + (uint32_t)(n * 2048 + ((u ^ (n & 7)) << 4)),
                 wsrc + (size_t)n * HID + u * 8);
        }
        asm volatile("cp.async.commit_group;" ::: "memory");
        asm volatile("cp.async.wait_group 0;" ::: "memory");
        __syncthreads();
    }

    // ---- per-thread constants
    const int wm   = wid * 32;                 // MMA warp m offset
    const int n0   = lane & 15;
    const int half = lane >> 4;                // 16B-unit parity within ldsm
    const int ar0  = wm + n0;
    const uint32_t a_sw = (uint32_t)(ar0 & 7);
    uint32_t b_base[4], b_sw[4];
    #pragma unroll
    for (int p = 0; p < 4; p++) {
        int n = p * 16 + n0;
        b_base[p] = sb + SM_W + (uint32_t)(n * 2048);
        b_sw[p]   = (uint32_t)(n & 7);
    }
    const int g = lane >> 2, tq = lane & 3;
    float2 bs[8];
    #pragma unroll
    for (int p = 0; p < 8; p++)
        bs[p] = *(const float2*)&g_bias[l * HID + nt * 64 + p * 8 + tq * 2];

    const bool fin_warp = is_mma && ((rank == 0) ? (wid < 2) : (wid >= 2));
    const int  fin0    = rank * 64;
    const int  nonfin0 = 64 - fin0;
    float* sP = (float*)(sh + SM_SP);
    const uint32_t peer_sp = mapa_u32(sb + SM_SP, (uint32_t)(rank ^ 1));

    // loader thread geometry
    const int lidx = tid - 128;                // 0..127 for loaders
    const int lr0  = (lidx >> 4) & 7;
    const int lc8  = lidx & 15;

    int fc[3]  = {0, 0, 0};   // consumer: completed full-phases per buffer
    int lfc[3] = {0, 0, 0};   // producer: fills per buffer

    unsigned bar = 0;

    #pragma unroll 1
    for (int s = 0; s <= T_STEPS + LAYERS - 1; s++) {
        const int t = s - l;
        const bool active = (t >= 0 && t < T_STEPS);
        if (active) {
            // A source: rank0 = layer input (x or act[l-1]); rank1 = own h
            const __half* src;
            const __half* actr = g_act[(s & 1) ^ 1];
            if (rank == 1)   src = actr + (size_t)l * BATCH * HID;
            else if (l == 0) src = g_xh + (size_t)t * BATCH * HID;
            else             src = actr + (size_t)(l - 1) * BATCH * HID;

            if (!is_mma) {
                // ================= PRODUCER =================
                const __half* sp0 = src + (size_t)lr0 * HID + lc8 * 8;
                #pragma unroll 1
                for (int ch = 0; ch < 8; ch++) {
                    int b = (ch < 3) ? ch : ((ch < 6) ? ch - 3 : ch - 6);
                    if (lfc[b] > 0)
                        mbar_wait(sb + SM_MBAR + 24 + b * 8, (lfc[b] - 1) & 1);
                    lfc[b]++;
                    uint32_t dst = sb + SM_A(b) +
                        (uint32_t)(lr0 * 256 + ((lc8 ^ lr0) << 4));
                    const __half* spc = sp0 + ch * 128;
                    #pragma unroll
                    for (int q = 0; q < 16; q++)
                        cp16(dst + q * 2048, spc + (size_t)q * 8 * HID);
                    cp_arrive(sb + SM_MBAR + b * 8);
                }
            } else {
                // ================= CONSUMER =================
                float acc[2][8][4];
                #pragma unroll
                for (int i = 0; i < 2; i++)
                    #pragma unroll
                    for (int j = 0; j < 8; j++)
                        #pragma unroll
                        for (int k = 0; k < 4; k++) acc[i][j][k] = 0.0f;

                uint32_t aF[2][2][4], bF[2][4][4];

                #pragma unroll 1
                for (int ch = 0; ch < 8; ch++) {
                    int b = (ch < 3) ? ch : ((ch < 6) ? ch - 3 : ch - 6);
                    mbar_wait(sb + SM_MBAR + b * 8, fc[b] & 1);
                    fc[b]++;

                    const uint32_t ab0 = sb + SM_A(b) + (uint32_t)(ar0 * 256);
                    const uint32_t ab1 = ab0 + 4096;
                    const int ub = ch * 16 + half;

                    // prologue frags j=0
                    {
                        uint32_t ao = (uint32_t)(((half) ^ a_sw) << 4);
                        ldsm4(aF[0][0], ab0 + ao);
                        ldsm4(aF[0][1], ab1 + ao);
                        #pragma unroll
                        for (int p = 0; p < 4; p++)
                            ldsm4(bF[0][p], b_base[p] +
                                  ((uint32_t)(ub ^ (int)b_sw[p]) << 4));
                    }
                    #pragma unroll
                    for (int j = 0; j < 8; j++) {
                        int cur = j & 1, nxt = cur ^ 1;
                        if (j < 7) {
                            int ul = (j + 1) * 2 + half;
                            uint32_t ao = (uint32_t)((ul ^ (int)a_sw) << 4);
                            ldsm4(aF[nxt][0], ab0 + ao);
                            ldsm4(aF[nxt][1], ab1 + ao);
                            int u = ch * 16 + ul;
                            #pragma unroll
                            for (int p = 0; p < 4; p++)
                                ldsm4(bF[nxt][p], b_base[p] +
                                      ((uint32_t)(u ^ (int)b_sw[p]) << 4));
                        }
                        #pragma unroll
                        for (int mt = 0; mt < 2; mt++)
                            #pragma unroll
                            for (int p = 0; p < 4; p++) {
                                mma16816(acc[mt][2 * p],     aF[cur][mt],
                                         bF[cur][p][0], bF[cur][p][2]);
                                mma16816(acc[mt][2 * p + 1], aF[cur][mt],
                                         bF[cur][p][1], bF[cur][p][3]);
                            }
                    }
                    mbar_arrive(sb + SM_MBAR + 24 + b * 8);
                }

                // all MMA warps past buffer reads before sP (aliases buf0)
                asm volatile("bar.sync 1, 128;" ::: "memory");

                if (!fin_warp) {
                    asm volatile("fence.proxy.async.shared::cta;" ::: "memory");
                    #pragma unroll
                    for (int mt = 0; mt < 2; mt++) {
                        int rr = wm + mt * 16 + g - nonfin0;
                        #pragma unroll
                        for (int p = 0; p < 8; p++) {
                            int c = p * 8 + tq * 2;
                            *(float2*)&sP[rr * 68 + c] =
                                make_float2(acc[mt][p][0], acc[mt][p][1]);
                            *(float2*)&sP[(rr + 8) * 68 + c] =
                                make_float2(acc[mt][p][2], acc[mt][p][3]);
                        }
                    }
                }
                asm volatile("barrier.cluster.arrive.aligned;" ::: "memory");
                asm volatile("barrier.cluster.wait.aligned;" ::: "memory");

                if (fin_warp) {
                    __half* actw = g_act[s & 1] + (size_t)l * BATCH * HID;
                    #pragma unroll
                    for (int mt = 0; mt < 2; mt++) {
                        int rg = wm + mt * 16 + g;
                        int rr = rg - fin0;
                        #pragma unroll
                        for (int p = 0; p < 8; p++) {
                            int c = p * 8 + tq * 2;
                            float2 p0 = ld_dsmem2(peer_sp + (uint32_t)(rr * 68 + c) * 4);
                            float2 p1 = ld_dsmem2(peer_sp + (uint32_t)((rr + 8) * 68 + c) * 4);
                            float v0 = tanhf(acc[mt][p][0] + p0.x + bs[p].x);
                            float v1 = tanhf(acc[mt][p][1] + p0.y + bs[p].y);
                            float v2 = tanhf(acc[mt][p][2] + p1.x + bs[p].x);
                            float v3 = tanhf(acc[mt][p][3] + p1.y + bs[p].y);
                            int cn = nt * 64 + c;
                            *(__half2*)&actw[(size_t)rg * HID + cn] =
                                __floats2half2_rn(v0, v1);
                            *(__half2*)&actw[(size_t)(rg + 8) * HID + cn] =
                                __floats2half2_rn(v2, v3);
                            if (l == 3) {
                                float* ob = out + (size_t)t * BATCH * HID + cn;
                                *(float2*)&ob[(size_t)rg * HID] = make_float2(v0, v1);
                                *(float2*)&ob[(size_t)(rg + 8) * HID] = make_float2(v2, v3);
                            }
                        }
                    }
                }
            }
            if (!is_mma) {  // producers join the cluster barrier too
                asm volatile("barrier.cluster.arrive.aligned;" ::: "memory");
                asm volatile("barrier.cluster.wait.aligned;" ::: "memory");
            }
        }
        grid_barrier(++bar, bx);
    }
}

// -------------------------------------------------------------- launch ----
extern "C" void kernel_launch(void* const* d_in, const int* in_sizes, int n_in,
                              void* d_out, int out_size)
{
    const float* x   = (const float*)d_in[0];
    const float* Wih = (const float*)d_in[1];
    const float* Whh = (const float*)d_in[2];
    const float* bih = (const float*)d_in[3];
    const float* bhh = (const float*)d_in[4];
    float* out = (float*)d_out;

    cudaFuncSetAttribute(rnn_persistent,
                         cudaFuncAttributeMaxDynamicSharedMemorySize, SMEM_BYTES);

    prep_kernel<<<2048, 256>>>(x, Wih, Whh, bih, bhh);
    rnn_persistent<<<NCTA, 256, SMEM_BYTES>>>(out);
}

// round 7
// speedup vs baseline: 1.2073x; 1.2073x over previous
#include <cuda_runtime.h>
#include <cuda_fp16.h>
#include <stdint.h>

// RNNWithCheckpoint: T=512, B=128, H=1024, L=4 multi-layer tanh RNN.
// R5: asynchronous per-layer pipeline (no global barrier). Each layer owns
// 32 CTAs (16 clusters x 2 k-ranks) and marches its own t=0..511 loop, gated
// by progress flags: own-layer >= t, upstream >= t+1, downstream >= t-2 (WAR).
// DSMEM reduce is push-model (remote st.shared::cluster, local read).
// fp16 mma.sync m16n8k16, fp32 accum; weights SMEM-resident.

#define T_STEPS 512
#define BATCH   128
#define HID     1024
#define LAYERS  4
#define NCTA    128

#define WROW 1032          // 1024 + 8 halves (bank-shift pad)
#define AROW 136           // 128 + 8 halves
#define SM_W  0            // 64 x WROW halves  = 132096 B
#define SM_A0 132096       // 128 x AROW halves = 34816 B
#define SM_A1 166912
#define SM_P  201728       // partial 64 x 68 fp32 = 17408 B (dedicated)
#define SMEM_BYTES 219136

// Static device scratch (no cudaMalloc allowed)
__device__ __align__(16) __half g_Wh[LAYERS * 2 * HID * HID];   // [l][ks][n][k]
__device__ __align__(16) __half g_xh[(size_t)T_STEPS * BATCH * HID];
__device__ __align__(16) float  g_bias[LAYERS * HID];
__device__ __align__(16) __half g_act[2][LAYERS * BATCH * HID]; // slot = t&1
__device__ unsigned g_flags[NCTA * 32];   // F[cta] = completed steps, 128B stride

// ------------------------------------------------------------- helpers ----
__device__ __forceinline__ uint32_t smem_u32(const void* p) {
    uint32_t a;
    asm("{ .reg .u64 t; cvta.to.shared.u64 t, %1; cvt.u32.u64 %0, t; }"
        : "=r"(a) : "l"(p));
    return a;
}
__device__ __forceinline__ void cp16(uint32_t dst, const void* src) {
    asm volatile("cp.async.cg.shared.global [%0], [%1], 16;"
                 :: "r"(dst), "l"(src) : "memory");
}
__device__ __forceinline__ void ldsm4(uint32_t* r, uint32_t a) {
    asm volatile("ldmatrix.sync.aligned.m8n8.x4.shared.b16 {%0,%1,%2,%3}, [%4];"
                 : "=r"(r[0]), "=r"(r[1]), "=r"(r[2]), "=r"(r[3]) : "r"(a));
}
__device__ __forceinline__ void mma16816(float* c, const uint32_t* a,
                                         uint32_t b0, uint32_t b1) {
    asm volatile(
        "mma.sync.aligned.m16n8k16.row.col.f32.f16.f16.f32 "
        "{%0,%1,%2,%3}, {%4,%5,%6,%7}, {%8,%9}, {%0,%1,%2,%3};"
        : "+f"(c[0]), "+f"(c[1]), "+f"(c[2]), "+f"(c[3])
        : "r"(a[0]), "r"(a[1]), "r"(a[2]), "r"(a[3]), "r"(b0), "r"(b1));
}
__device__ __forceinline__ uint32_t mapa_u32(uint32_t a, uint32_t rk) {
    uint32_t o;
    asm("mapa.shared::cluster.u32 %0, %1, %2;" : "=r"(o) : "r"(a), "r"(rk));
    return o;
}
__device__ __forceinline__ void st_dsmem2(uint32_t a, float x, float y) {
    asm volatile("st.shared::cluster.v2.f32 [%0], {%1,%2};"
                 :: "r"(a), "f"(x), "f"(y) : "memory");
}

// Poll 32 flags of CTA group [base32, base32+32) until all >= target.
__device__ __forceinline__ void poll_group(int base32, int target, int lane)
{
    if (target <= 0) return;
    const volatile unsigned* f = g_flags;
    unsigned tgt = (unsigned)target;
    for (;;) {
        bool ok = f[(base32 + lane) * 32] >= tgt;
        if (__all_sync(0xffffffffu, ok)) break;
        __nanosleep(50);
    }
}

// ---------------------------------------------------------------- prep ----
__global__ void __launch_bounds__(256) prep_kernel(
    const float* __restrict__ x,
    const float* __restrict__ Wih, const float* __restrict__ Whh,
    const float* __restrict__ bih, const float* __restrict__ bhh)
{
    int tid  = blockIdx.x * blockDim.x + threadIdx.x;
    int nthr = gridDim.x * blockDim.x;
    const int NW = LAYERS * HID * HID;
    for (int i = tid; i < NW; i += nthr) {
        int l  = i >> 20;
        int nk = i & (HID * HID - 1);
        g_Wh[((size_t)(l * 2 + 0) << 20) + nk] = __float2half(Wih[i]);
        g_Wh[((size_t)(l * 2 + 1) << 20) + nk] = __float2half(Whh[i]);
    }
    const size_t NX4 = (size_t)T_STEPS * BATCH * HID / 4;
    for (size_t i = tid; i < NX4; i += nthr) {
        float4 v = *(const float4*)(x + i * 4);
        *(__half2*)&g_xh[i * 4]     = __floats2half2_rn(v.x, v.y);
        *(__half2*)&g_xh[i * 4 + 2] = __floats2half2_rn(v.z, v.w);
    }
    for (int i = tid; i < LAYERS * HID; i += nthr) g_bias[i] = bih[i] + bhh[i];
    for (int i = tid; i < LAYERS * BATCH * HID; i += nthr) {
        g_act[0][i] = __float2half(0.0f);
        g_act[1][i] = __float2half(0.0f);
    }
    for (int i = tid; i < NCTA * 32; i += nthr) g_flags[i] = 0;
}

// ----------------------------------------------------------- persistent ---
// bx: l = bx>>5, nt = (bx>>1)&15, rank = bx&1 (cluster pair = the 2 k-halves).
__global__ void __launch_bounds__(256) __cluster_dims__(2, 1, 1)
rnn_persistent(float* __restrict__ out)
{
    extern __shared__ char sh[];
    const uint32_t sb = smem_u32(sh);

    const int bx   = blockIdx.x;
    const int l    = bx >> 5;
    const int nt   = (bx >> 1) & 15;
    const int rank = bx & 1;
    const int tid  = threadIdx.x;
    const int wid  = tid >> 5, lane = tid & 31;
    const int g    = lane >> 2, tq = lane & 3;
    const int wm   = (wid >> 1) * 32;   // 4 m-groups of 32 rows
    const int wn   = (wid & 1) * 32;    // 2 n-groups of 32 cols

    // ---- resident weight slice: 64 n-rows x 1024 k halves
    {
        const __half* wsrc = g_Wh + (((size_t)(l * 2 + rank) * HID) + nt * 64) * HID;
        for (int i = tid; i < 8192; i += 256) {
            int r = i >> 7, c = i & 127;
            cp16(sb + SM_W + (uint32_t)(r * WROW + c * 8) * 2,
                 wsrc + (size_t)r * HID + c * 8);
        }
        asm volatile("cp.async.commit_group;" ::: "memory");
        asm volatile("cp.async.wait_group 0;" ::: "memory");
        __syncthreads();
    }

    // per-thread constant addresses
    const uint32_t aoff = (uint32_t)(((wm + (lane & 15)) * AROW + (lane >> 4) * 8) * 2);
    uint32_t wb[2];
    #pragma unroll
    for (int p = 0; p < 2; p++)
        wb[p] = sb + SM_W +
                (uint32_t)(((wn + p * 16 + (lane & 15)) * WROW + (lane >> 4) * 8) * 2);
    float2 bs[4];
    #pragma unroll
    for (int nti = 0; nti < 4; nti++)
        bs[nti] = *(const float2*)&g_bias[l * HID + nt * 64 + wn + nti * 8 + tq * 2];

    const int  fin0    = rank * 64;      // rows this CTA finalizes
    const int  nonfin0 = 64 - fin0;      // rows pushed to peer (= peer fin0)
    const bool fin_w   = (rank == 0) ? (wm < 64) : (wm >= 64);
    float* sP = (float*)(sh + SM_P);
    const uint32_t peer_sp = mapa_u32(sb + SM_P, (uint32_t)(rank ^ 1));

    #pragma unroll 1
    for (int t = 0; t < T_STEPS; t++) {
        // ---- dependency gate (3 warps poll in parallel) ----
        if (wid == 0)               poll_group(l * 32, t, lane);              // own
        else if (wid == 1 && l > 0) poll_group((l - 1) * 32, t + 1, lane);    // up
        else if (wid == 2 && l < 3) poll_group((l + 1) * 32, t - 1, lane);    // WAR
        __syncthreads();

        // A source: rank0 = layer input h[l-1][t] (slot t&1) or x;
        //           rank1 = own h[l][t-1] (slot (t&1)^1)
        const __half* src;
        if (rank == 1)   src = g_act[(t & 1) ^ 1] + (size_t)l * BATCH * HID;
        else if (l == 0) src = g_xh + (size_t)t * BATCH * HID;
        else             src = g_act[t & 1] + (size_t)(l - 1) * BATCH * HID;

        // ---- prologue: chunks 0,1 ----
        #pragma unroll
        for (int c0 = 0; c0 < 2; c0++) {
            uint32_t dst = sb + (c0 ? SM_A1 : SM_A0);
            const __half* sp = src + c0 * 128;
            for (int i = tid; i < 2048; i += 256) {
                int r = i >> 4, c = i & 15;
                cp16(dst + (uint32_t)(r * AROW + c * 8) * 2,
                     sp + (size_t)r * HID + c * 8);
            }
            asm volatile("cp.async.commit_group;" ::: "memory");
        }

        float acc[2][4][4];
        #pragma unroll
        for (int i = 0; i < 2; i++)
            #pragma unroll
            for (int j = 0; j < 4; j++)
                #pragma unroll
                for (int k = 0; k < 4; k++) acc[i][j][k] = 0.0f;

        #pragma unroll 2
        for (int ch = 0; ch < 8; ch++) {
            if (ch < 7) asm volatile("cp.async.wait_group 1;" ::: "memory");
            else        asm volatile("cp.async.wait_group 0;" ::: "memory");
            __syncthreads();

            uint32_t ab = sb + ((ch & 1) ? SM_A1 : SM_A0) + aoff;
            uint32_t kb = (uint32_t)(ch * 256);
            #pragma unroll
            for (int j = 0; j < 8; j++) {
                uint32_t a0[4], a1[4], b0[4], b1[4];
                ldsm4(a0, ab + j * 32);
                ldsm4(a1, ab + 16 * AROW * 2 + j * 32);
                ldsm4(b0, wb[0] + kb + j * 32);
                ldsm4(b1, wb[1] + kb + j * 32);
                mma16816(acc[0][0], a0, b0[0], b0[2]);
                mma16816(acc[0][1], a0, b0[1], b0[3]);
                mma16816(acc[0][2], a0, b1[0], b1[2]);
                mma16816(acc[0][3], a0, b1[1], b1[3]);
                mma16816(acc[1][0], a1, b0[0], b0[2]);
                mma16816(acc[1][1], a1, b0[1], b0[3]);
                mma16816(acc[1][2], a1, b1[0], b1[2]);
                mma16816(acc[1][3], a1, b1[1], b1[3]);
            }
            __syncthreads();
            if (ch < 6) {   // refill this buffer with chunk ch+2
                uint32_t dst = sb + ((ch & 1) ? SM_A1 : SM_A0);
                const __half* sp = src + (ch + 2) * 128;
                for (int i = tid; i < 2048; i += 256) {
                    int r = i >> 4, c = i & 15;
                    cp16(dst + (uint32_t)(r * AROW + c * 8) * 2,
                         sp + (size_t)r * HID + c * 8);
                }
                asm volatile("cp.async.commit_group;" ::: "memory");
            }
        }

        // ---- PUSH partial rows to peer's sP (remote write, latency hidden)
        if (!fin_w) {
            #pragma unroll
            for (int mt = 0; mt < 2; mt++) {
                int rr = wm + mt * 16 + g - nonfin0;   // index in peer's fin range
                #pragma unroll
                for (int nti = 0; nti < 4; nti++) {
                    int c = wn + nti * 8 + tq * 2;
                    st_dsmem2(peer_sp + (uint32_t)(rr * 68 + c) * 4,
                              acc[mt][nti][0], acc[mt][nti][1]);
                    st_dsmem2(peer_sp + (uint32_t)((rr + 8) * 68 + c) * 4,
                              acc[mt][nti][2], acc[mt][nti][3]);
                }
            }
        }
        asm volatile("barrier.cluster.arrive.aligned;" ::: "memory");
        asm volatile("barrier.cluster.wait.aligned;" ::: "memory");

        // ---- finalize: local sP read + bias + tanh -> act slot t&1 (+ out)
        if (fin_w) {
            __half* actw = g_act[t & 1] + (size_t)l * BATCH * HID;
            #pragma unroll
            for (int mt = 0; mt < 2; mt++) {
                int rg = wm + mt * 16 + g;
                int rr = rg - fin0;
                #pragma unroll
                for (int nti = 0; nti < 4; nti++) {
                    int c = wn + nti * 8 + tq * 2;
                    float2 p0 = *(const float2*)&sP[rr * 68 + c];
                    float2 p1 = *(const float2*)&sP[(rr + 8) * 68 + c];
                    float v0 = tanhf(acc[mt][nti][0] + p0.x + bs[nti].x);
                    float v1 = tanhf(acc[mt][nti][1] + p0.y + bs[nti].y);
                    float v2 = tanhf(acc[mt][nti][2] + p1.x + bs[nti].x);
                    float v3 = tanhf(acc[mt][nti][3] + p1.y + bs[nti].y);
                    int cn = nt * 64 + c;
                    *(__half2*)&actw[(size_t)rg * HID + cn] =
                        __floats2half2_rn(v0, v1);
                    *(__half2*)&actw[(size_t)(rg + 8) * HID + cn] =
                        __floats2half2_rn(v2, v3);
                    if (l == 3) {
                        float* ob = out + (size_t)t * BATCH * HID + cn;
                        *(float2*)&ob[(size_t)rg * HID] = make_float2(v0, v1);
                        *(float2*)&ob[(size_t)(rg + 8) * HID] = make_float2(v2, v3);
                    }
                }
            }
        }

        // ---- publish progress ----
        __syncthreads();
        if (tid == 0) {
            __threadfence();
            atomicExch(&g_flags[bx * 32], (unsigned)(t + 1));
        }
    }
}

// -------------------------------------------------------------- launch ----
extern "C" void kernel_launch(void* const* d_in, const int* in_sizes, int n_in,
                              void* d_out, int out_size)
{
    const float* x   = (const float*)d_in[0];
    const float* Wih = (const float*)d_in[1];
    const float* Whh = (const float*)d_in[2];
    const float* bih = (const float*)d_in[3];
    const float* bhh = (const float*)d_in[4];
    float* out = (float*)d_out;

    cudaFuncSetAttribute(rnn_persistent,
                         cudaFuncAttributeMaxDynamicSharedMemorySize, SMEM_BYTES);

    prep_kernel<<<2048, 256>>>(x, Wih, Whh, bih, bhh);
    rnn_persistent<<<NCTA, 256, SMEM_BYTES>>>(out);
}